// round 12
// baseline (speedup 1.0000x reference)
#include <cuda_runtime.h>
#include <cuda_bf16.h>
#include <cstdint>

// Problem constants
#define M_ROWS  200000      // BATCH * SIM_T
#define K_DIM   784
#define N1      100
#define T_STEPS 2000
#define BATCH   100
#define N2      10
#define NCHUNKS 1563        // ceil(200000/128)

// Scratch.
// g_z1 layout: [t][batch][c]  (row r' = t*100 + b). Padded to t=2008.
__device__ float g_z1[(size_t)2008 * BATCH * N1];           // 80 MB
__device__ float g_T1[(size_t)M_ROWS * N1];                 // 80 MB  [b][t][c]
__device__ int   g_flag[1600];                              // per-chunk done flags
__device__ __align__(16) __nv_bfloat16 g_W1h[112 * K_DIM];
__device__ __align__(16) __nv_bfloat16 g_W1l[112 * K_DIM];

// ---------------------------------------------------------------------------
// helpers
// ---------------------------------------------------------------------------
__device__ __forceinline__ unsigned pack_bf16x2(float fhi, float flo) {
    unsigned r;
    asm("cvt.rn.bf16x2.f32 %0, %1, %2;" : "=r"(r) : "f"(fhi), "f"(flo));
    return r;
}
__device__ __forceinline__ void mma_bf16(float* c, const unsigned* a,
                                         unsigned b0, unsigned b1) {
    asm("mma.sync.aligned.m16n8k16.row.col.f32.bf16.bf16.f32 "
        "{%0,%1,%2,%3}, {%4,%5,%6,%7}, {%8,%9}, {%0,%1,%2,%3};"
        : "+f"(c[0]), "+f"(c[1]), "+f"(c[2]), "+f"(c[3])
        : "r"(a[0]), "r"(a[1]), "r"(a[2]), "r"(a[3]), "r"(b0), "r"(b1));
}

// ---------------------------------------------------------------------------
// K0: convert W1 -> bf16 hi/lo (112 rows) + reset chunk flags
// ---------------------------------------------------------------------------
__global__ void w1_convert_kernel(const float* __restrict__ W1) {
    int idx = blockIdx.x * 256 + threadIdx.x;
    if (idx < 1600) g_flag[idx] = 0;
    if (idx >= 112 * K_DIM) return;
    int r = idx / K_DIM;
    float w = (r < N1) ? W1[idx] : 0.f;
    __nv_bfloat16 hb = __float2bfloat16_rn(w);
    float hf = __bfloat162float(hb);
    g_W1h[idx] = hb;
    g_W1l[idx] = __float2bfloat16_rn(w - hf);
}

// ---------------------------------------------------------------------------
// HH step math (exact round-9 version: 4 EX2 batched, 4 RCP batched)
// ---------------------------------------------------------------------------
__device__ __forceinline__ float ex2a(float x) {
    float r; asm("ex2.approx.f32 %0, %1;" : "=f"(r) : "f"(x)); return r;
}
__device__ __forceinline__ float rcpa(float x) {
    float r; asm("rcp.approx.f32 %0, %1;" : "=f"(r) : "f"(x)); return r;
}

#define L9   0.1602994489863f
#define L12  0.1202245867397f
#define L3   0.4808983469589f
#define BH_C 0.0023508962f
#define S0V  9.357622969e-14f

__device__ __forceinline__ float hh_step_t(float zk, float& V, float& m, float& n, float& h) {
    float mm   = m * m;
    float pow1 = 40.f * (mm * m) * h;
    float nn   = n * n;
    float pow2 = 35.f * (nn * nn);
    float Gs = 0.005f * (pow1 + pow2 + 0.3f);
    float E  = fmaf(pow1, 55.f, fmaf(pow2, -77.f, -19.5f));
    float num = fmaf(V, (1.f - Gs), 0.01f * (E + 1.5f + zk));
    float Vn = num * rcpa(1.f + Gs);

    float dM = Vn + 35.f;
    float dN = Vn - 25.f;
    float uM = ex2a(dM * L9);
    float uN = ex2a(dN * L9);
    float w  = ex2a((Vn + 90.f) * L12);
    float eS = ex2a((20.f - Vn) * L3);

    float um1M = uM - 1.f;
    float sM = 0.005f * dM * fmaf(0.182f, uM, 0.124f);
    float um1N = uN - 1.f;
    float sN = 0.005f * dN * fmaf(0.02f, uN, 0.002f);
    float sH = fmaf(0.005f * BH_C, w * w, 0.00125f);

    float rM = rcpa(um1M + sM);
    float rN = rcpa(um1N + sN);
    float rH = rcpa(w + sH);
    float rS = rcpa(1.f + eS);

    float mN = fmaf(0.00182f * dM, uM, (um1M - sM) * m) * rM;
    float nN = fmaf(0.0002f * dN, uN, (um1N - sN) * n) * rN;
    float hN = fmaf(w - sH, h, 0.0025f) * rH;

    if (Vn == 25.f)  nN = fmaf(0.99901f, n, 0.0018f) * (1.f / 1.00099f);
    if (Vn == -35.f) mN = fmaf(0.98623f, m, 0.01638f) * (1.f / 1.01377f);

    m = mN; n = nN; h = hN;
    V = Vn;
    return rS;
}

// ---------------------------------------------------------------------------
// wait until chunk flags [clo, chi] are all set (warp-parallel volatile poll)
// ---------------------------------------------------------------------------
__device__ __forceinline__ void wait_chunks(int clo, int chi) {
    const int lane = threadIdx.x & 31;
    for (int base = clo; base <= chi; base += 32) {
        int cid = min(base + lane, chi);
        while (__any_sync(0xffffffffu, ((volatile int*)g_flag)[cid] == 0))
            __nanosleep(64);
    }
    __threadfence();
}

// ---------------------------------------------------------------------------
// K1: FULLY FUSED gemm + layer1 + z2 + layer2.
//   blocks 0..99 (256 thr), batch b = blk, window-pipelined 3 roles:
//     warps 0-3 (tid<128, act tid<100): layer-1 scan window i (waits on GEMM
//                chunk flags; T1 -> global, coalesced).
//     warps 4-6 (tid 128-223): z2 matvec for window i-1, T1 (global, L1-hot,
//                same-block visibility via the per-window __syncthreads)
//                -> smem ring z2s[(i-1)%3].
//     warp  7   (tid 224-255, lanes<10): layer-2 HH for window i-2 -> out.
//   One __syncthreads per WINDOW (42 total) — not per step.
//   blocks 100..1662: GEMM chunk (blk-100), publishes g_flag[chunk].
// ---------------------------------------------------------------------------
#define NSTAGE 49
#define WIN    50
#define NWIN   40

__global__ void __launch_bounds__(256, 2)
fused_all(const float* __restrict__ A, const float* __restrict__ W2,
          float* __restrict__ out) {
    __shared__ unsigned Ahs[2][128 * 8];
    __shared__ unsigned Als[2][128 * 8];
    __shared__ unsigned Bhs[2][112 * 8];
    __shared__ unsigned Bls[2][112 * 8];
    __shared__ float W2s[N1][12];
    __shared__ float z2s[3][WIN][N2];

    const int blk = blockIdx.x;
    const int tid = threadIdx.x;

    if (blk < BATCH) {
        // ============== pipelined scan block, batch b ==============
        const int b = blk;

        // --- producer state (warps 0-3) ---
        const bool act = (tid < N1);
        const float* zl = g_z1 + (size_t)b * N1 + tid;     // z1[t][b][c]
        float* ts = g_T1 + (size_t)b * T_STEPS * N1 + tid;
        float V1 = -70.f, m1 = 0.f, n1 = 0.f, h1 = 1.f;
        float p0 = 0.f, p1 = 0.f, p2 = 0.f, p3 = 0.f;

        // --- L2 state (warp 7) ---
        const int lane7 = tid - 224;
        float V2 = -70.f, m2 = 0.f, n2 = 0.f, h2 = 1.f;

        if (tid < 128) {
            wait_chunks(0, 3);                  // z1 t-rows 0..3
            if (act) {
                ts[0] = S0V;                    // T1 row 0
                p0 = zl[0];
                p1 = zl[10000];
                p2 = zl[20000];
                p3 = zl[30000];
            }
            ts += N1;                           // store slot for row 1
            zl += 40000;
        } else if (tid < 224) {
            // load W2s (read first at iteration 1, after iteration-0 barrier)
            for (int ii = tid - 128; ii < N1 * 12; ii += 96) {
                int k = ii / 12, o = ii - 12 * k;
                W2s[k][o] = (o < N2) ? W2[o * N1 + k] : 0.f;
            }
        } else if (lane7 < N2) {
            out[(size_t)b * T_STEPS * N2 + lane7] = S0V;
        }

#pragma unroll 1
        for (int i = 0; i < NWIN + 2; i++) {
            if (tid < 128) {
                // ---- layer-1 window i ----
                if (i < NWIN) {
                    int tlo = i * WIN + 4;
                    int thi = min(i * WIN + 53, T_STEPS - 1);
                    if (tlo <= T_STEPS - 1)
                        wait_chunks((tlo * 100) / 128, (thi * 100 + 99) / 128);
                    const int steps = (i == NWIN - 1) ? 49 : 50;
                    if (act) {
#pragma unroll 2
                        for (int j = 0; j < steps; j++) {
                            float zc = p0;
                            p0 = p1; p1 = p2; p2 = p3; p3 = *zl; zl += 10000;
                            *ts = hh_step_t(zc, V1, m1, n1, h1);
                            ts += N1;
                        }
                    }
                }
            } else if (tid < 224) {
                // ---- z2 matvec window i-1 ----
                if (i >= 1 && i <= NWIN) {
                    const int w = i - 1;
                    float* zb = &z2s[w % 3][0][0];
                    for (int idx = tid - 128; idx < WIN * N2; idx += 96) {
                        int j = idx / N2, o = idx - N2 * j;
                        const float* tr =
                            g_T1 + (size_t)(b * T_STEPS + w * WIN + j) * N1;
                        float acc = 0.f;
#pragma unroll 4
                        for (int k = 0; k < N1; k++)
                            acc = fmaf(tr[k], W2s[k][o], acc);
                        zb[j * N2 + o] = acc;
                    }
                }
            } else {
                // ---- layer-2 HH window i-2 ----
                if (i >= 2 && lane7 < N2) {
                    const int w2 = i - 2;
                    const int steps = (w2 == NWIN - 1) ? 49 : 50;
                    const float* zb = &z2s[w2 % 3][0][lane7];
                    float* op = out + ((size_t)b * T_STEPS + w2 * WIN + 1) * N2 + lane7;
#pragma unroll 2
                    for (int j = 0; j < steps; j++) {
                        *op = hh_step_t(zb[j * N2], V2, m2, n2, h2);
                        op += N2;
                    }
                }
            }
            __syncthreads();
        }
        return;
    }

    // ================= GEMM chunk =================
    const int chunk = blk - BATCH;
    const int row0  = chunk * 128;

    const int warp = tid >> 5, lane = tid & 31;
    const int g    = lane >> 2, tig = lane & 3;
    const int wm   = (warp >> 1) * 32;
    const int wn   = (warp & 1) * 56;

    // per-thread A row pointers (r' = t*100+b -> A row b*2000+t)
    const float* aptr[2];
    bool av[2];
    {
#pragma unroll
        for (int i = 0; i < 2; i++) {
            int idx = tid + i * 256;
            int rp = row0 + (idx >> 2);
            av[i] = rp < M_ROWS;
            int rc = av[i] ? rp : 0;
            int t = rc / 100;
            int bb = rc - t * 100;
            aptr[i] = A + (size_t)(bb * 2000 + t) * K_DIM + (idx & 3) * 4;
        }
    }

    float acc[2][7][4];
#pragma unroll
    for (int i = 0; i < 2; i++)
#pragma unroll
        for (int j = 0; j < 7; j++)
#pragma unroll
            for (int q = 0; q < 4; q++) acc[i][j][q] = 0.f;

    float4 va[2];
    unsigned vbh[4], vbl[4];

    auto ldg_stage = [&](int s) {
        int k0 = s * 16;
#pragma unroll
        for (int i = 0; i < 2; i++)
            va[i] = av[i] ? *(const float4*)(aptr[i] + k0)
                          : make_float4(0.f, 0.f, 0.f, 0.f);
#pragma unroll
        for (int i = 0; i < 4; i++) {
            int idx = tid + i * 256;
            if (idx < 896) {
                int r = idx >> 3, j = idx & 7;
                size_t off = (size_t)r * (K_DIM / 2) + (k0 >> 1) + j;
                vbh[i] = ((const unsigned*)g_W1h)[off];
                vbl[i] = ((const unsigned*)g_W1l)[off];
            }
        }
    };
    auto sts_stage = [&](int buf) {
#pragma unroll
        for (int i = 0; i < 2; i++) {
            int idx = tid + i * 256;
            int r = idx >> 2, q = idx & 3;
            float4 v = va[i];
            unsigned h0 = pack_bf16x2(v.y, v.x);
            unsigned h1 = pack_bf16x2(v.w, v.z);
            float f0h = __uint_as_float(h0 << 16);
            float f1h = __uint_as_float(h0 & 0xffff0000u);
            float f2h = __uint_as_float(h1 << 16);
            float f3h = __uint_as_float(h1 & 0xffff0000u);
            unsigned l0 = pack_bf16x2(v.y - f1h, v.x - f0h);
            unsigned l1 = pack_bf16x2(v.w - f3h, v.z - f2h);
            int sw = r & 7;
            Ahs[buf][r * 8 + ((2 * q)     ^ sw)] = h0;
            Ahs[buf][r * 8 + ((2 * q + 1) ^ sw)] = h1;
            Als[buf][r * 8 + ((2 * q)     ^ sw)] = l0;
            Als[buf][r * 8 + ((2 * q + 1) ^ sw)] = l1;
        }
#pragma unroll
        for (int i = 0; i < 4; i++) {
            int idx = tid + i * 256;
            if (idx < 896) {
                int r = idx >> 3, j = idx & 7;
                Bhs[buf][r * 8 + (j ^ (r & 7))] = vbh[i];
                Bls[buf][r * 8 + (j ^ (r & 7))] = vbl[i];
            }
        }
    };

    ldg_stage(0);
    sts_stage(0);
    __syncthreads();

#pragma unroll 1
    for (int s = 0; s < NSTAGE; s++) {
        if (s + 1 < NSTAGE) ldg_stage(s + 1);

        const int buf = s & 1;
        unsigned a_h[2][4], a_l[2][4];
#pragma unroll
        for (int mt = 0; mt < 2; mt++) {
            int r0 = wm + mt * 16 + g, r1 = r0 + 8;
            int s0 = r0 & 7, s1 = r1 & 7;
            a_h[mt][0] = Ahs[buf][r0 * 8 + (tig ^ s0)];
            a_h[mt][1] = Ahs[buf][r1 * 8 + (tig ^ s1)];
            a_h[mt][2] = Ahs[buf][r0 * 8 + ((tig + 4) ^ s0)];
            a_h[mt][3] = Ahs[buf][r1 * 8 + ((tig + 4) ^ s1)];
            a_l[mt][0] = Als[buf][r0 * 8 + (tig ^ s0)];
            a_l[mt][1] = Als[buf][r1 * 8 + (tig ^ s1)];
            a_l[mt][2] = Als[buf][r0 * 8 + ((tig + 4) ^ s0)];
            a_l[mt][3] = Als[buf][r1 * 8 + ((tig + 4) ^ s1)];
        }
#pragma unroll
        for (int nt = 0; nt < 7; nt++) {
            int n = wn + nt * 8 + g;
            int sn = n & 7;
            unsigned b0h = Bhs[buf][n * 8 + (tig ^ sn)];
            unsigned b1h = Bhs[buf][n * 8 + ((tig + 4) ^ sn)];
            unsigned b0l = Bls[buf][n * 8 + (tig ^ sn)];
            unsigned b1l = Bls[buf][n * 8 + ((tig + 4) ^ sn)];
#pragma unroll
            for (int mt = 0; mt < 2; mt++) {
                mma_bf16(acc[mt][nt], a_h[mt], b0h, b1h);
                mma_bf16(acc[mt][nt], a_h[mt], b0l, b1l);
                mma_bf16(acc[mt][nt], a_l[mt], b0h, b1h);
            }
        }

        if (s + 1 < NSTAGE) sts_stage((s + 1) & 1);
        __syncthreads();
    }

#pragma unroll
    for (int mt = 0; mt < 2; mt++) {
#pragma unroll
        for (int nt = 0; nt < 7; nt++) {
            int c = wn + nt * 8 + 2 * tig;
            if (c >= 99) continue;
            int r0g = row0 + wm + mt * 16 + g;
            if (r0g < M_ROWS) {
                float2 v = make_float2(acc[mt][nt][0], acc[mt][nt][1]);
                *(float2*)(g_z1 + (size_t)r0g * N1 + c) = v;
            }
            if (r0g + 8 < M_ROWS) {
                float2 v = make_float2(acc[mt][nt][2], acc[mt][nt][3]);
                *(float2*)(g_z1 + (size_t)(r0g + 8) * N1 + c) = v;
            }
        }
    }

    // publish chunk
    __threadfence();
    __syncthreads();
    if (tid == 0) atomicExch(&g_flag[chunk], 1);
}

// ---------------------------------------------------------------------------
extern "C" void kernel_launch(void* const* d_in, const int* in_sizes, int n_in,
                              void* d_out, int out_size) {
    const float* batch = (const float*)d_in[0];   // (100, 2000, 784)
    const float* W1    = (const float*)d_in[1];   // (100, 784)
    const float* W2    = (const float*)d_in[2];   // (10, 100)
    float* out = (float*)d_out;                   // (100, 2000, 10)

    w1_convert_kernel<<<(112 * K_DIM + 255) / 256, 256>>>(W1);
    fused_all<<<BATCH + NCHUNKS, 256>>>(batch, W2, out);
}